// round 11
// baseline (speedup 1.0000x reference)
#include <cuda_runtime.h>
#include <math.h>
#include <stdint.h>

#ifndef M_PI
#define M_PI 3.14159265358979323846
#endif

#define CC    256       // channels (circulant size)
#define HP    3136      // 56*56 pixels per batch
#define NB    64        // batch
#define NTOT  (NB * HP) // 200704 global pixel rows

// ---- tcgen05 path geometry (128 px per CTA, 2 CTAs/SM) ----
#define MPIX  128                 // pixels per CTA tile (MMA M)
#define NCTAS (NTOT / MPIX)       // 1568
#define KC    32                  // K elems per chunk (128 B rows of tf32)
#define NCHUNK (CC / KC)          // 8
#define BEXT_ROWS 480             // 224 + 256 rows of extended circulant B

// idesc: dtype F32 (1<<4), atype TF32 (2<<7), btype TF32 (2<<10),
// N=256 -> 32<<17, M=128 -> 8<<24
#define IDESC_TF32 ((1u<<4) | (2u<<7) | (2u<<10) | (32u<<17) | (8u<<24))

// tc smem layout (bytes, dynamic)
#define OFF_TMEMPTR 0
#define OFF_FREEA   8            // freeA0 @8, freeA1 @16 (count 1, commit-driven)
#define OFF_FULL    24           // full0 @24, full1 @32  (count 8, producer arrivals)
#define OFF_DMB     40           // D-done @40 (count 1)
#define OFF_MCOL    1024         // 256 floats: per-CTA inverse-circulant column
#define OFF_ABUF0   2048
#define OFF_ABUF1   18432
#define OFF_BEXT    34816
#define SMEM_TOTAL  96256

// ---- SIMT fallback geometry ----
#define TPIX  64
#define NTILE (HP / TPIX)         // 49
#define SIMT_SMEM ((2 * CC + CC * TPIX) * (int)sizeof(float))

__device__ float g_Mcol[CC];
__device__ int   g_use_tc;

// Only compilation passes with the sm_103a/sm_100a arch-specific feature set
// may ever see tcgen05 PTX (plain sm_103 ptxas rejects it at compile time).
#if defined(__CUDA_ARCH_FEAT_SM103_ALL) || defined(__CUDA_ARCH_FEAT_SM100_ALL)
#define HAS_TCGEN05 1
#else
#define HAS_TCGEN05 0
#endif

// ---------------------------------------------------------------------------
// helpers usable on any target
// ---------------------------------------------------------------------------
__device__ __forceinline__ uint32_t to_tf32(float x) {
    uint32_t u;
    asm("cvt.rna.tf32.f32 %0, %1;" : "=r"(u) : "f"(x));
    return u;
}
#define SWZ128(o) ((o) ^ (((o) >> 3) & 0x70))

// volatile global load: pins issue order so the prefetch stream stays ahead
// of mbar waits.
__device__ __forceinline__ float ldg_v(const float* p) {
    float v;
    asm volatile("ld.global.nc.f32 %0, [%1];" : "=f"(v) : "l"(p));
    return v;
}

// ---------------------------------------------------------------------------
// Setup kernel (fallback path only): spectral inverse of (I - T) + probe.
// ---------------------------------------------------------------------------
__global__ void setup_kernel(const float* __restrict__ dampp,
                             const float* __restrict__ widthp) {
    __shared__ float ct[CC];
    __shared__ float row0s[CC];
    __shared__ float mus[CC];

    const int t = threadIdx.x;
    if (t == 0) g_use_tc = HAS_TCGEN05;

    const float damp  = *dampp;
    const float width = *widthp;

    ct[t] = (float)cos(2.0 * M_PI * (double)t / 256.0);

    int xe = min(t, CC - t);
    float r = 0.0f;
    if (xe >= 1 && xe <= 31) {
        double w2 = (double)width * (double)width;
        double x2 = (double)xe * (double)xe;
        r = (float)((double)damp * (1.0 - x2 / w2) * exp(-x2 / (2.0 * w2)));
    }
    row0s[t] = r;
    __syncthreads();

    float s = 0.0f;
    for (int d = 0; d < CC; d++) s += row0s[d] * ct[(t * d) & 255];
    mus[t] = 1.0f / (1.0f - s);
    __syncthreads();

    float mc = 0.0f;
    for (int m = 0; m < CC; m++) mc += mus[m] * ct[(t * m) & 255];
    g_Mcol[t] = mc * (1.0f / 256.0f);
}

// ===========================================================================
// SIMT fallback (known-good R1 kernel); runs only when tcgen05 is unavailable
// ===========================================================================
__device__ __forceinline__ unsigned long long ffma2(unsigned long long a,
                                                    unsigned long long b,
                                                    unsigned long long c) {
    unsigned long long d;
    asm("fma.rn.f32x2 %0, %1, %2, %3;" : "=l"(d) : "l"(a), "l"(b), "l"(c));
    return d;
}
__device__ __forceinline__ unsigned long long pack2(float v) {
    unsigned long long d;
    asm("mov.b64 %0, {%1, %1};" : "=l"(d) : "f"(v));
    return d;
}

__global__ __launch_bounds__(256, 2)
void inhib_simt_kernel(const float* __restrict__ x, float* __restrict__ y) {
    if (g_use_tc) return;

    extern __shared__ float smemf[];
    float* Ms2 = smemf;
    float* Xs  = smemf + 2 * CC;

    const int t = threadIdx.x;
    Ms2[t]      = g_Mcol[t];
    Ms2[t + CC] = g_Mcol[t];

    const int b  = blockIdx.y;
    const int p0 = blockIdx.x * TPIX;
    const float* xb = x + (size_t)b * CC * HP + p0;

    const int lr = t >> 4;
    const int lc = (t & 15) * 4;
    #pragma unroll
    for (int rr = 0; rr < 16; rr++) {
        int row = rr * 16 + lr;
        float4 v = *(const float4*)(xb + (size_t)row * HP + lc);
        *(float4*)&Xs[row * TPIX + lc] = v;
    }
    __syncthreads();

    const int i0  = (t >> 3) * 8;
    const int pp0 = (t & 7) * 8;

    unsigned long long acc[8][4];
    #pragma unroll
    for (int ii = 0; ii < 8; ii++)
        #pragma unroll
        for (int pp = 0; pp < 4; pp++) acc[ii][pp] = 0ull;

    #pragma unroll 8
    for (int j = 0; j < CC; j++) {
        const int base = (i0 - j) & 255;
        unsigned long long a2[8];
        #pragma unroll
        for (int ii = 0; ii < 8; ii++) a2[ii] = pack2(Ms2[base + ii]);

        const ulonglong2 bv0 = *(const ulonglong2*)&Xs[j * TPIX + pp0];
        const ulonglong2 bv1 = *(const ulonglong2*)&Xs[j * TPIX + pp0 + 4];
        const unsigned long long b2[4] = {bv0.x, bv0.y, bv1.x, bv1.y};

        #pragma unroll
        for (int ii = 0; ii < 8; ii++)
            #pragma unroll
            for (int pp = 0; pp < 4; pp++)
                acc[ii][pp] = ffma2(a2[ii], b2[pp], acc[ii][pp]);
    }

    float* yb = y + (size_t)b * CC * HP + p0;
    #pragma unroll
    for (int ii = 0; ii < 8; ii++) {
        float* yr = yb + (size_t)(i0 + ii) * HP + pp0;
        #pragma unroll
        for (int pp = 0; pp < 4; pp++)
            *(unsigned long long*)(yr + pp * 2) = acc[ii][pp];
    }
}

// ===========================================================================
// tcgen05 tf32 path (compiled only under the sm_103a feature set)
// ===========================================================================
#if HAS_TCGEN05
__device__ __forceinline__ uint32_t smem_u32(const void* p) {
    uint32_t a;
    asm("{ .reg .u64 t; cvta.to.shared.u64 t, %1; cvt.u32.u64 %0, t; }"
        : "=r"(a) : "l"(p));
    return a;
}
__device__ __forceinline__ uint32_t elect_one() {
    uint32_t p;
    asm volatile("{ .reg .pred p; elect.sync _|p, 0xFFFFFFFF; selp.b32 %0,1,0,p; }"
                 : "=r"(p));
    return p;
}
static __device__ __forceinline__ uint64_t make_desc(uint32_t addr) {
    // SW128 K-major: layout=2, version=1, SBO=64, LBO=1
    const uint64_t base = (uint64_t(2) << 61) | (uint64_t(1) << 46) |
                          (uint64_t(64) << 32) | (uint64_t(1) << 16);
    return base | ((uint64_t)(addr >> 4) & 0x3FFF);
}
__device__ __forceinline__ void mma_tf32_ss(uint32_t d_tmem, uint64_t a_desc,
                                            uint64_t b_desc, uint32_t en) {
    asm volatile(
        "{\n\t"
        ".reg .pred p;\n\t"
        "setp.ne.u32 p, %5, 0;\n\t"
        "tcgen05.mma.cta_group::1.kind::tf32 [%0], %1, %2, %3, {%4, %4, %4, %4}, p;\n\t"
        "}"
        :: "r"(d_tmem), "l"(a_desc), "l"(b_desc), "r"(IDESC_TF32),
           "r"(0u), "r"(en)
        : "memory");
}
#define TMEM_ALLOC(sp, n) \
    asm volatile("tcgen05.alloc.cta_group::1.sync.aligned.shared::cta.b32 [%0], %1;" \
                 :: "r"(sp), "r"((uint32_t)(n)) : "memory")
#define TMEM_DEALLOC(tb, n) \
    asm volatile("tcgen05.dealloc.cta_group::1.sync.aligned.b32 %0, %1;" \
                 :: "r"(tb), "r"((uint32_t)(n)))
#define TMEM_RELINQ() \
    asm volatile("tcgen05.relinquish_alloc_permit.cta_group::1.sync.aligned;")
#define TC_COMMIT(mb) \
    asm volatile("tcgen05.commit.cta_group::1.mbarrier::arrive::one.shared::cluster.b64 [%0];" \
                 :: "r"(mb) : "memory")
#define TC_FENCE_AFTER() asm volatile("tcgen05.fence::after_thread_sync;" ::: "memory")
#define TC_WAIT_LD()     asm volatile("tcgen05.wait::ld.sync.aligned;" ::: "memory")
#define FENCE_ASYNC()    asm volatile("fence.proxy.async.shared::cta;" ::: "memory")
#define MBAR_INIT(mb, n) \
    asm volatile("mbarrier.init.shared.b64 [%0], %1;" :: "r"(mb), "r"((uint32_t)(n)) : "memory")
#define MBAR_ARRIVE(mb) \
    asm volatile("mbarrier.arrive.shared.b64 _, [%0];" :: "r"(mb) : "memory")

__device__ __forceinline__ void mbar_wait(uint32_t mb, uint32_t parity) {
    asm volatile(
        "{\n\t"
        ".reg .pred P1;\n\t"
        "WL_%=:\n\t"
        "mbarrier.try_wait.parity.acquire.cta.shared::cta.b64 P1, [%0], %1, 0x989680;\n\t"
        "@P1 bra.uni WD_%=;\n\t"
        "bra.uni WL_%=;\n\t"
        "WD_%=:\n\t"
        "}"
        :: "r"(mb), "r"(parity) : "memory");
}
__device__ __forceinline__ void ldtm_x32(uint32_t* r, uint32_t ta) {
    asm volatile(
        "tcgen05.ld.sync.aligned.32x32b.x32.b32 "
        "{%0,%1,%2,%3,%4,%5,%6,%7,%8,%9,%10,%11,%12,%13,%14,%15,"
        "%16,%17,%18,%19,%20,%21,%22,%23,%24,%25,%26,%27,%28,%29,%30,%31}, [%32];"
        : "=r"(r[0]), "=r"(r[1]), "=r"(r[2]), "=r"(r[3]),
          "=r"(r[4]), "=r"(r[5]), "=r"(r[6]), "=r"(r[7]),
          "=r"(r[8]), "=r"(r[9]), "=r"(r[10]), "=r"(r[11]),
          "=r"(r[12]), "=r"(r[13]), "=r"(r[14]), "=r"(r[15]),
          "=r"(r[16]), "=r"(r[17]), "=r"(r[18]), "=r"(r[19]),
          "=r"(r[20]), "=r"(r[21]), "=r"(r[22]), "=r"(r[23]),
          "=r"(r[24]), "=r"(r[25]), "=r"(r[26]), "=r"(r[27]),
          "=r"(r[28]), "=r"(r[29]), "=r"(r[30]), "=r"(r[31])
        : "r"(ta));
}
#endif  // HAS_TCGEN05

__global__ __launch_bounds__(256, 2)
void inhib_tc_kernel(const float* __restrict__ x, float* __restrict__ y,
                     const float* __restrict__ dampp,
                     const float* __restrict__ widthp) {
#if HAS_TCGEN05
    extern __shared__ char smem[];
    const uint32_t sb = smem_u32(smem);
    const int t = threadIdx.x;
    const int wid = t >> 5;
    const int lane = t & 31;

    // ---- per-thread staging geometry ----
    const int tp = t & 127;          // tile pixel-row this thread stages
    const int jh = t >> 7;           // 0/1: which 16 j's
    int g0 = blockIdx.x * MPIX + tp;
    int b0 = g0 / HP;
    int pix0 = g0 - b0 * HP;
    const float* xrow = x + (size_t)b0 * (CC * HP) + pix0 + (size_t)(jh * 16) * HP;

    // ---- 3-stage register pipeline: prefetch chunks 0 and 1 now ----
    float v[3][16];
    #pragma unroll
    for (int s = 0; s < 2; s++) {
        const float* xc = xrow + (size_t)(32 * s) * HP;
        #pragma unroll
        for (int jj = 0; jj < 16; jj++)
            v[s][jj] = ldg_v(xc + (size_t)jj * HP);
    }

    if (wid == 0) {
        TMEM_ALLOC(sb + OFF_TMEMPTR, 256);
        TMEM_RELINQ();
    }
    if (t == 0) {
        MBAR_INIT(sb + OFF_FREEA + 0, 1);  // A buf 0 free (commit-driven)
        MBAR_INIT(sb + OFF_FREEA + 8, 1);  // A buf 1 free
        MBAR_INIT(sb + OFF_FULL + 0, 8);   // A buf 0 staged (8 warp arrivals)
        MBAR_INIT(sb + OFF_FULL + 8, 8);   // A buf 1 staged
        MBAR_INIT(sb + OFF_DMB, 1);        // all MMAs done
    }

    // ---- in-CTA spectral setup (single-launch: no separate setup kernel) ----
    // Scratch aliases A-buffer 0: fully consumed before staging's first write
    // (which happens after the prologue __syncthreads below).
    {
        float* ctS   = (float*)(smem + OFF_ABUF0);           // 256 f
        float* row0S = (float*)(smem + OFF_ABUF0 + 1024);    // 256 f
        float* musS  = (float*)(smem + OFF_ABUF0 + 2048);    // 256 f
        float* mcolS = (float*)(smem + OFF_MCOL);            // 256 f (kept)

        const float damp  = *dampp;
        const float width = *widthp;

        // cos(2*pi*t/256) = cospi(t/128); exact argument reduction
        ctS[t] = cospif((float)t * (1.0f / 128.0f));

        int xe = min(t, CC - t);
        float r = 0.0f;
        if (xe >= 1 && xe <= 31) {
            float w2 = width * width;
            float x2 = (float)(xe * xe);
            r = damp * (1.0f - x2 / w2) * expf(-x2 / (2.0f * w2));
        }
        row0S[t] = r;
        __syncthreads();

        float s0 = 0.0f, s1 = 0.0f;
        for (int d = 0; d < CC; d += 2) {
            s0 += row0S[d]     * ctS[(t * d) & 255];
            s1 += row0S[d + 1] * ctS[(t * (d + 1)) & 255];
        }
        musS[t] = 1.0f / (1.0f - (s0 + s1));
        __syncthreads();

        float m0 = 0.0f, m1 = 0.0f;
        for (int m = 0; m < CC; m += 2) {
            m0 += musS[m]     * ctS[(t * m) & 255];
            m1 += musS[m + 1] * ctS[(t * (m + 1)) & 255];
        }
        mcolS[t] = (m0 + m1) * (1.0f / 256.0f);
        __syncthreads();
    }

    // B_ext[rr][jj] = tf32(mcol[(rr - 224 - jj) & 255]), rr in [0,480);
    // 4 taps packed per STS.128 (conflict-free across the warp).
    {
        const float* mcolS = (const float*)(smem + OFF_MCOL);
        #pragma unroll
        for (int it = 0; it < 15; it++) {
            int g = t + 256 * it;          // group of 4 consecutive jj
            int rr = g >> 3;
            int j0 = (g & 7) * 4;
            int base = rr - 224 - j0;
            uint4 w;
            w.x = to_tf32(mcolS[(base)     & 255]);
            w.y = to_tf32(mcolS[(base - 1) & 255]);
            w.z = to_tf32(mcolS[(base - 2) & 255]);
            w.w = to_tf32(mcolS[(base - 3) & 255]);
            *(uint4*)(smem + OFF_BEXT + SWZ128(rr * 128 + j0 * 4)) = w;
        }
    }
    FENCE_ASYNC();
    __syncthreads();   // mbars + B_ext visible; scratch free for staging

    uint32_t tmem;
    asm volatile("ld.shared.b32 %0, [%1];" : "=r"(tmem) : "r"(sb + OFF_TMEMPTR));

    // ---- main loop: producer warps never block on each other; only the
    //      MMA-issuing warp (warp 0) waits for all 8 staging arrivals ----
    #pragma unroll
    for (int c = 0; c < NCHUNK; c++) {
        if (c + 2 < NCHUNK) {
            const float* xn = xrow + (size_t)(32 * (c + 2)) * HP;
            #pragma unroll
            for (int jj = 0; jj < 16; jj++)
                v[(c + 2) % 3][jj] = ldg_v(xn + (size_t)jj * HP);
        }

        const int buf = c & 1;
        const uint32_t abuf_off = buf ? OFF_ABUF1 : OFF_ABUF0;
        if (c >= 2)
            mbar_wait(sb + OFF_FREEA + 8 * buf, ((c - 2) >> 1) & 1);

        // stage chunk c: cvt to tf32, pack 4-wide, conflict-free STS.128
        #pragma unroll
        for (int q = 0; q < 4; q++) {
            uint4 w;
            w.x = to_tf32(v[c % 3][q * 4 + 0]);
            w.y = to_tf32(v[c % 3][q * 4 + 1]);
            w.z = to_tf32(v[c % 3][q * 4 + 2]);
            w.w = to_tf32(v[c % 3][q * 4 + 3]);
            const int jl = jh * 16 + q * 4;
            *(uint4*)(smem + abuf_off + SWZ128(tp * 128 + jl * 4)) = w;
        }
        FENCE_ASYNC();
        __syncwarp();
        if (elect_one())
            MBAR_ARRIVE(sb + OFF_FULL + 8 * buf);

        if (wid == 0) {
            mbar_wait(sb + OFF_FULL + 8 * buf, (c >> 1) & 1);
            if (elect_one()) {
                uint64_t ad = make_desc(sb + abuf_off);
                uint64_t bd = make_desc(sb + OFF_BEXT + (224 - 32 * c) * 128);
                #pragma unroll
                for (int kk = 0; kk < 4; kk++)
                    mma_tf32_ss(tmem, ad + kk * 2, bd + kk * 2,
                                (c | kk) ? 1u : 0u);
                TC_COMMIT(sb + OFF_FREEA + 8 * buf);
                if (c == NCHUNK - 1)
                    TC_COMMIT(sb + OFF_DMB);
            }
        }
    }

    // ---- epilogue: all warps wait for MMA completion, then stream D out ----
    mbar_wait(sb + OFF_DMB, 0);
    TC_FENCE_AFTER();
    {
        const int sub = wid & 3;
        const int cb0 = (wid >> 2) * 4;
        int g = blockIdx.x * MPIX + sub * 32 + lane;
        int b = g / HP;
        int pix = g - b * HP;
        float* ybase = y + (size_t)b * (CC * HP) + pix;

        for (int cb = cb0; cb < cb0 + 4; cb++) {
            uint32_t r[32];
            ldtm_x32(r, tmem + cb * 32);
            TC_WAIT_LD();
            #pragma unroll
            for (int q = 0; q < 32; q++)
                ybase[(size_t)(cb * 32 + q) * HP] = __uint_as_float(r[q]);
        }
    }

    __syncthreads();
    if (wid == 0)
        TMEM_DEALLOC(tmem, 256);
#endif  // HAS_TCGEN05
}

// ---------------------------------------------------------------------------
extern "C" void kernel_launch(void* const* d_in, const int* in_sizes, int n_in,
                              void* d_out, int out_size) {
    const float* act = nullptr;
    const float* damp = nullptr;
    const float* width = nullptr;
    for (int i = 0; i < n_in; i++) {
        if (in_sizes[i] > 1024) act = (const float*)d_in[i];
        else if (!damp)  damp  = (const float*)d_in[i];
        else if (!width) width = (const float*)d_in[i];
    }
    float* out = (float*)d_out;

    // Host-side detection: the tc kernel stub (non-sm_103a pass) compiles to a
    // handful of registers; the real one needs far more.
    cudaFuncAttributes fa;
    bool have_tc = (cudaFuncGetAttributes(&fa, inhib_tc_kernel) == cudaSuccess)
                   && fa.numRegs > 24;

    if (have_tc) {
        // single launch: spectral setup is computed inside each CTA
        cudaFuncSetAttribute(inhib_tc_kernel,
                             cudaFuncAttributeMaxDynamicSharedMemorySize, SMEM_TOTAL);
        inhib_tc_kernel<<<NCTAS, 256, SMEM_TOTAL>>>(act, out, damp, width);
    } else {
        setup_kernel<<<1, 256>>>(damp, width);
        cudaFuncSetAttribute(inhib_simt_kernel,
                             cudaFuncAttributeMaxDynamicSharedMemorySize, SIMT_SMEM);
        dim3 sgrid(NTILE, NB);
        inhib_simt_kernel<<<sgrid, 256, SIMT_SMEM>>>(act, out);
    }
}

// round 12
// speedup vs baseline: 1.5598x; 1.5598x over previous
#include <cuda_runtime.h>
#include <math.h>
#include <stdint.h>

#ifndef M_PI
#define M_PI 3.14159265358979323846
#endif

#define CC    256       // channels (circulant size)
#define HP    3136      // 56*56 pixels per batch
#define NB    64        // batch
#define NTOT  (NB * HP) // 200704 global pixel rows

// ---- tcgen05 path geometry (128 px per CTA, 2 CTAs/SM) ----
#define MPIX  128                 // pixels per CTA tile (MMA M)
#define NCTAS (NTOT / MPIX)       // 1568
#define KC    32                  // K elems per chunk (128 B rows of tf32)
#define NCHUNK (CC / KC)          // 8
#define BEXT_ROWS 480             // 224 + 256 rows of extended circulant B

// idesc: dtype F32 (1<<4), atype TF32 (2<<7), btype TF32 (2<<10),
// N=256 -> 32<<17, M=128 -> 8<<24
#define IDESC_TF32 ((1u<<4) | (2u<<7) | (2u<<10) | (32u<<17) | (8u<<24))

// tc smem layout (bytes, dynamic)
#define OFF_TMEMPTR 0
#define OFF_FREEA   8            // freeA0 @8, freeA1 @16 (count 1, commit-driven)
#define OFF_FULL    24           // full0 @24, full1 @32  (count 8, producer arrivals)
#define OFF_DMB     40           // D-done @40 (count 1)
#define OFF_RICK    512          // 32 floats: ricker taps r(e)
#define OFF_MCOL    1024         // 256 floats: inverse-circulant column
#define OFF_ABUF0   2048
#define OFF_ABUF1   18432
#define OFF_BEXT    34816
#define SMEM_TOTAL  96256

// ---- SIMT fallback geometry ----
#define TPIX  64
#define NTILE (HP / TPIX)         // 49
#define SIMT_SMEM ((2 * CC + CC * TPIX) * (int)sizeof(float))

__device__ float g_Mcol[CC];
__device__ int   g_use_tc;

// Only compilation passes with the sm_103a/sm_100a arch-specific feature set
// may ever see tcgen05 PTX (plain sm_103 ptxas rejects it at compile time).
#if defined(__CUDA_ARCH_FEAT_SM103_ALL) || defined(__CUDA_ARCH_FEAT_SM100_ALL)
#define HAS_TCGEN05 1
#else
#define HAS_TCGEN05 0
#endif

// ---------------------------------------------------------------------------
// helpers usable on any target
// ---------------------------------------------------------------------------
__device__ __forceinline__ uint32_t to_tf32(float x) {
    uint32_t u;
    asm("cvt.rna.tf32.f32 %0, %1;" : "=r"(u) : "f"(x));
    return u;
}
#define SWZ128(o) ((o) ^ (((o) >> 3) & 0x70))

// volatile global load: pins issue order so the prefetch stream stays ahead
// of mbar waits.
__device__ __forceinline__ float ldg_v(const float* p) {
    float v;
    asm volatile("ld.global.nc.f32 %0, [%1];" : "=f"(v) : "l"(p));
    return v;
}

// ---------------------------------------------------------------------------
// Setup kernel (fallback path only): spectral inverse of (I - T) + probe.
// ---------------------------------------------------------------------------
__global__ void setup_kernel(const float* __restrict__ dampp,
                             const float* __restrict__ widthp) {
    __shared__ float ct[CC];
    __shared__ float row0s[CC];
    __shared__ float mus[CC];

    const int t = threadIdx.x;
    if (t == 0) g_use_tc = HAS_TCGEN05;

    const float damp  = *dampp;
    const float width = *widthp;

    ct[t] = (float)cos(2.0 * M_PI * (double)t / 256.0);

    int xe = min(t, CC - t);
    float r = 0.0f;
    if (xe >= 1 && xe <= 31) {
        double w2 = (double)width * (double)width;
        double x2 = (double)xe * (double)xe;
        r = (float)((double)damp * (1.0 - x2 / w2) * exp(-x2 / (2.0 * w2)));
    }
    row0s[t] = r;
    __syncthreads();

    float s = 0.0f;
    for (int d = 0; d < CC; d++) s += row0s[d] * ct[(t * d) & 255];
    mus[t] = 1.0f / (1.0f - s);
    __syncthreads();

    float mc = 0.0f;
    for (int m = 0; m < CC; m++) mc += mus[m] * ct[(t * m) & 255];
    g_Mcol[t] = mc * (1.0f / 256.0f);
}

// ===========================================================================
// SIMT fallback (known-good R1 kernel); runs only when tcgen05 is unavailable
// ===========================================================================
__device__ __forceinline__ unsigned long long ffma2(unsigned long long a,
                                                    unsigned long long b,
                                                    unsigned long long c) {
    unsigned long long d;
    asm("fma.rn.f32x2 %0, %1, %2, %3;" : "=l"(d) : "l"(a), "l"(b), "l"(c));
    return d;
}
__device__ __forceinline__ unsigned long long pack2(float v) {
    unsigned long long d;
    asm("mov.b64 %0, {%1, %1};" : "=l"(d) : "f"(v));
    return d;
}

__global__ __launch_bounds__(256, 2)
void inhib_simt_kernel(const float* __restrict__ x, float* __restrict__ y) {
    if (g_use_tc) return;

    extern __shared__ float smemf[];
    float* Ms2 = smemf;
    float* Xs  = smemf + 2 * CC;

    const int t = threadIdx.x;
    Ms2[t]      = g_Mcol[t];
    Ms2[t + CC] = g_Mcol[t];

    const int b  = blockIdx.y;
    const int p0 = blockIdx.x * TPIX;
    const float* xb = x + (size_t)b * CC * HP + p0;

    const int lr = t >> 4;
    const int lc = (t & 15) * 4;
    #pragma unroll
    for (int rr = 0; rr < 16; rr++) {
        int row = rr * 16 + lr;
        float4 v = *(const float4*)(xb + (size_t)row * HP + lc);
        *(float4*)&Xs[row * TPIX + lc] = v;
    }
    __syncthreads();

    const int i0  = (t >> 3) * 8;
    const int pp0 = (t & 7) * 8;

    unsigned long long acc[8][4];
    #pragma unroll
    for (int ii = 0; ii < 8; ii++)
        #pragma unroll
        for (int pp = 0; pp < 4; pp++) acc[ii][pp] = 0ull;

    #pragma unroll 8
    for (int j = 0; j < CC; j++) {
        const int base = (i0 - j) & 255;
        unsigned long long a2[8];
        #pragma unroll
        for (int ii = 0; ii < 8; ii++) a2[ii] = pack2(Ms2[base + ii]);

        const ulonglong2 bv0 = *(const ulonglong2*)&Xs[j * TPIX + pp0];
        const ulonglong2 bv1 = *(const ulonglong2*)&Xs[j * TPIX + pp0 + 4];
        const unsigned long long b2[4] = {bv0.x, bv0.y, bv1.x, bv1.y};

        #pragma unroll
        for (int ii = 0; ii < 8; ii++)
            #pragma unroll
            for (int pp = 0; pp < 4; pp++)
                acc[ii][pp] = ffma2(a2[ii], b2[pp], acc[ii][pp]);
    }

    float* yb = y + (size_t)b * CC * HP + p0;
    #pragma unroll
    for (int ii = 0; ii < 8; ii++) {
        float* yr = yb + (size_t)(i0 + ii) * HP + pp0;
        #pragma unroll
        for (int pp = 0; pp < 4; pp++)
            *(unsigned long long*)(yr + pp * 2) = acc[ii][pp];
    }
}

// ===========================================================================
// tcgen05 tf32 path (compiled only under the sm_103a feature set)
// ===========================================================================
#if HAS_TCGEN05
__device__ __forceinline__ uint32_t smem_u32(const void* p) {
    uint32_t a;
    asm("{ .reg .u64 t; cvta.to.shared.u64 t, %1; cvt.u32.u64 %0, t; }"
        : "=r"(a) : "l"(p));
    return a;
}
__device__ __forceinline__ uint32_t elect_one() {
    uint32_t p;
    asm volatile("{ .reg .pred p; elect.sync _|p, 0xFFFFFFFF; selp.b32 %0,1,0,p; }"
                 : "=r"(p));
    return p;
}
static __device__ __forceinline__ uint64_t make_desc(uint32_t addr) {
    // SW128 K-major: layout=2, version=1, SBO=64, LBO=1
    const uint64_t base = (uint64_t(2) << 61) | (uint64_t(1) << 46) |
                          (uint64_t(64) << 32) | (uint64_t(1) << 16);
    return base | ((uint64_t)(addr >> 4) & 0x3FFF);
}
__device__ __forceinline__ void mma_tf32_ss(uint32_t d_tmem, uint64_t a_desc,
                                            uint64_t b_desc, uint32_t en) {
    asm volatile(
        "{\n\t"
        ".reg .pred p;\n\t"
        "setp.ne.u32 p, %5, 0;\n\t"
        "tcgen05.mma.cta_group::1.kind::tf32 [%0], %1, %2, %3, {%4, %4, %4, %4}, p;\n\t"
        "}"
        :: "r"(d_tmem), "l"(a_desc), "l"(b_desc), "r"(IDESC_TF32),
           "r"(0u), "r"(en)
        : "memory");
}
#define TMEM_ALLOC(sp, n) \
    asm volatile("tcgen05.alloc.cta_group::1.sync.aligned.shared::cta.b32 [%0], %1;" \
                 :: "r"(sp), "r"((uint32_t)(n)) : "memory")
#define TMEM_DEALLOC(tb, n) \
    asm volatile("tcgen05.dealloc.cta_group::1.sync.aligned.b32 %0, %1;" \
                 :: "r"(tb), "r"((uint32_t)(n)))
#define TMEM_RELINQ() \
    asm volatile("tcgen05.relinquish_alloc_permit.cta_group::1.sync.aligned;")
#define TC_COMMIT(mb) \
    asm volatile("tcgen05.commit.cta_group::1.mbarrier::arrive::one.shared::cluster.b64 [%0];" \
                 :: "r"(mb) : "memory")
#define TC_FENCE_AFTER() asm volatile("tcgen05.fence::after_thread_sync;" ::: "memory")
#define TC_WAIT_LD()     asm volatile("tcgen05.wait::ld.sync.aligned;" ::: "memory")
#define FENCE_ASYNC()    asm volatile("fence.proxy.async.shared::cta;" ::: "memory")
#define MBAR_INIT(mb, n) \
    asm volatile("mbarrier.init.shared.b64 [%0], %1;" :: "r"(mb), "r"((uint32_t)(n)) : "memory")
#define MBAR_ARRIVE(mb) \
    asm volatile("mbarrier.arrive.shared.b64 _, [%0];" :: "r"(mb) : "memory")

__device__ __forceinline__ void mbar_wait(uint32_t mb, uint32_t parity) {
    asm volatile(
        "{\n\t"
        ".reg .pred P1;\n\t"
        "WL_%=:\n\t"
        "mbarrier.try_wait.parity.acquire.cta.shared::cta.b64 P1, [%0], %1, 0x989680;\n\t"
        "@P1 bra.uni WD_%=;\n\t"
        "bra.uni WL_%=;\n\t"
        "WD_%=:\n\t"
        "}"
        :: "r"(mb), "r"(parity) : "memory");
}
__device__ __forceinline__ void ldtm_x32(uint32_t* r, uint32_t ta) {
    asm volatile(
        "tcgen05.ld.sync.aligned.32x32b.x32.b32 "
        "{%0,%1,%2,%3,%4,%5,%6,%7,%8,%9,%10,%11,%12,%13,%14,%15,"
        "%16,%17,%18,%19,%20,%21,%22,%23,%24,%25,%26,%27,%28,%29,%30,%31}, [%32];"
        : "=r"(r[0]), "=r"(r[1]), "=r"(r[2]), "=r"(r[3]),
          "=r"(r[4]), "=r"(r[5]), "=r"(r[6]), "=r"(r[7]),
          "=r"(r[8]), "=r"(r[9]), "=r"(r[10]), "=r"(r[11]),
          "=r"(r[12]), "=r"(r[13]), "=r"(r[14]), "=r"(r[15]),
          "=r"(r[16]), "=r"(r[17]), "=r"(r[18]), "=r"(r[19]),
          "=r"(r[20]), "=r"(r[21]), "=r"(r[22]), "=r"(r[23]),
          "=r"(r[24]), "=r"(r[25]), "=r"(r[26]), "=r"(r[27]),
          "=r"(r[28]), "=r"(r[29]), "=r"(r[30]), "=r"(r[31])
        : "r"(ta));
}
#endif  // HAS_TCGEN05

__global__ __launch_bounds__(256, 2)
void inhib_tc_kernel(const float* __restrict__ x, float* __restrict__ y,
                     const float* __restrict__ dampp,
                     const float* __restrict__ widthp) {
#if HAS_TCGEN05
    extern __shared__ char smem[];
    const uint32_t sb = smem_u32(smem);
    const int t = threadIdx.x;
    const int wid = t >> 5;
    const int lane = t & 31;

    // ---- per-thread staging geometry ----
    const int tp = t & 127;          // tile pixel-row this thread stages
    const int jh = t >> 7;           // 0/1: which 16 j's
    int g0 = blockIdx.x * MPIX + tp;
    int b0 = g0 / HP;
    int pix0 = g0 - b0 * HP;
    const float* xrow = x + (size_t)b0 * (CC * HP) + pix0 + (size_t)(jh * 16) * HP;

    // ---- 3-stage register pipeline: prefetch chunks 0 and 1 now ----
    float v[3][16];
    #pragma unroll
    for (int s = 0; s < 2; s++) {
        const float* xc = xrow + (size_t)(32 * s) * HP;
        #pragma unroll
        for (int jj = 0; jj < 16; jj++)
            v[s][jj] = ldg_v(xc + (size_t)jj * HP);
    }

    if (wid == 0) {
        TMEM_ALLOC(sb + OFF_TMEMPTR, 256);
        TMEM_RELINQ();
    }
    if (t == 0) {
        MBAR_INIT(sb + OFF_FREEA + 0, 1);  // A buf 0 free (commit-driven)
        MBAR_INIT(sb + OFF_FREEA + 8, 1);  // A buf 1 free
        MBAR_INIT(sb + OFF_FULL + 0, 8);   // A buf 0 staged (8 warp arrivals)
        MBAR_INIT(sb + OFF_FULL + 8, 8);   // A buf 1 staged
        MBAR_INIT(sb + OFF_DMB, 1);        // all MMAs done
    }

    // ---- in-CTA spectral setup (fast: symmetry + Chebyshev recurrence) ----
    // lambda_t = 1 - 2*sum_{e=1..31} r(e)*cos(e*theta_t),  theta_t = 2*pi*t/256
    // mcol[t]  = (mu0 + 2*sum_{m=1..128} mu_m*c_m - mu128*(-1)^t) / 256
    // cos terms via 4-chain Chebyshev: c_{k+4} = 2*cos(4*theta)*c_k - c_{k-4}.
    // Only uniform (broadcast) LDS; no gathers.
    {
        float* rS   = (float*)(smem + OFF_RICK);   // 32 f: ricker taps
        float* musS = (float*)(smem + OFF_ABUF0);  // 256 f (scratch, aliased)
        float* mcolS = (float*)(smem + OFF_MCOL);  // 256 f (kept)

        const float damp  = *dampp;
        const float width = *widthp;

        if (t < 32) {
            float r = 0.0f;
            if (t >= 1) {
                float w2 = width * width;
                float x2 = (float)(t * t);
                r = damp * (1.0f - x2 / w2) * expf(-x2 / (2.0f * w2));
            }
            rS[t] = r;
        }

        const float a  = (float)t * (1.0f / 128.0f);   // theta/pi
        const float c1 = cospif(a);
        const float c2 = cospif(2.0f * a);
        const float c3 = cospif(3.0f * a);
        const float c4 = cospif(4.0f * a);
        const float k4 = 2.0f * c4;
        __syncthreads();

        // phase 1: lambda_t (31 terms)
        {
            float cur[4] = {c1, c2, c3, c4};
            float prv[4] = {c3, c2, c1, 1.0f};
            float s = 0.0f;
            #pragma unroll
            for (int i = 0; i < 8; i++) {
                #pragma unroll
                for (int r = 0; r < 4; r++) {
                    const int e = 1 + r + 4 * i;
                    if (e <= 31) s += rS[e] * cur[r];
                    float nx = k4 * cur[r] - prv[r];
                    prv[r] = cur[r];
                    cur[r] = nx;
                }
            }
            musS[t] = 1.0f / (1.0f - 2.0f * s);
        }
        __syncthreads();

        // phase 2: mcol[t] (128 terms, chains cover m = 1..128 exactly once)
        {
            float cur[4] = {c1, c2, c3, c4};
            float prv[4] = {c3, c2, c1, 1.0f};
            float S = 0.0f;
            #pragma unroll 8
            for (int i = 0; i < 32; i++) {
                #pragma unroll
                for (int r = 0; r < 4; r++) {
                    const int m = 1 + r + 4 * i;
                    S += musS[m] * cur[r];
                    float nx = k4 * cur[r] - prv[r];
                    prv[r] = cur[r];
                    cur[r] = nx;
                }
            }
            const float par = (t & 1) ? -1.0f : 1.0f;
            mcolS[t] = (musS[0] + 2.0f * S - musS[128] * par) * (1.0f / 256.0f);
        }
        __syncthreads();   // mcol ready; musS scratch (A-buf 0) now dead
    }

    // B_ext[rr][jj] = tf32(mcol[(rr - 224 - jj) & 255]), rr in [0,480);
    // 4 taps packed per STS.128 (conflict-free across the warp).
    {
        const float* mcolS = (const float*)(smem + OFF_MCOL);
        #pragma unroll
        for (int it = 0; it < 15; it++) {
            int g = t + 256 * it;          // group of 4 consecutive jj
            int rr = g >> 3;
            int j0 = (g & 7) * 4;
            int base = rr - 224 - j0;
            uint4 w;
            w.x = to_tf32(mcolS[(base)     & 255]);
            w.y = to_tf32(mcolS[(base - 1) & 255]);
            w.z = to_tf32(mcolS[(base - 2) & 255]);
            w.w = to_tf32(mcolS[(base - 3) & 255]);
            *(uint4*)(smem + OFF_BEXT + SWZ128(rr * 128 + j0 * 4)) = w;
        }
    }
    FENCE_ASYNC();
    __syncthreads();   // mbars + B_ext visible; scratch free for staging

    uint32_t tmem;
    asm volatile("ld.shared.b32 %0, [%1];" : "=r"(tmem) : "r"(sb + OFF_TMEMPTR));

    // ---- main loop: producer warps never block on each other; only the
    //      MMA-issuing warp (warp 0) waits for all 8 staging arrivals ----
    #pragma unroll
    for (int c = 0; c < NCHUNK; c++) {
        if (c + 2 < NCHUNK) {
            const float* xn = xrow + (size_t)(32 * (c + 2)) * HP;
            #pragma unroll
            for (int jj = 0; jj < 16; jj++)
                v[(c + 2) % 3][jj] = ldg_v(xn + (size_t)jj * HP);
        }

        const int buf = c & 1;
        const uint32_t abuf_off = buf ? OFF_ABUF1 : OFF_ABUF0;
        if (c >= 2)
            mbar_wait(sb + OFF_FREEA + 8 * buf, ((c - 2) >> 1) & 1);

        // stage chunk c: cvt to tf32, pack 4-wide, conflict-free STS.128
        #pragma unroll
        for (int q = 0; q < 4; q++) {
            uint4 w;
            w.x = to_tf32(v[c % 3][q * 4 + 0]);
            w.y = to_tf32(v[c % 3][q * 4 + 1]);
            w.z = to_tf32(v[c % 3][q * 4 + 2]);
            w.w = to_tf32(v[c % 3][q * 4 + 3]);
            const int jl = jh * 16 + q * 4;
            *(uint4*)(smem + abuf_off + SWZ128(tp * 128 + jl * 4)) = w;
        }
        FENCE_ASYNC();
        __syncwarp();
        if (elect_one())
            MBAR_ARRIVE(sb + OFF_FULL + 8 * buf);

        if (wid == 0) {
            mbar_wait(sb + OFF_FULL + 8 * buf, (c >> 1) & 1);
            if (elect_one()) {
                uint64_t ad = make_desc(sb + abuf_off);
                uint64_t bd = make_desc(sb + OFF_BEXT + (224 - 32 * c) * 128);
                #pragma unroll
                for (int kk = 0; kk < 4; kk++)
                    mma_tf32_ss(tmem, ad + kk * 2, bd + kk * 2,
                                (c | kk) ? 1u : 0u);
                TC_COMMIT(sb + OFF_FREEA + 8 * buf);
                if (c == NCHUNK - 1)
                    TC_COMMIT(sb + OFF_DMB);
            }
        }
    }

    // ---- epilogue: all warps wait for MMA completion, then stream D out ----
    mbar_wait(sb + OFF_DMB, 0);
    TC_FENCE_AFTER();
    {
        const int sub = wid & 3;
        const int cb0 = (wid >> 2) * 4;
        int g = blockIdx.x * MPIX + sub * 32 + lane;
        int b = g / HP;
        int pix = g - b * HP;
        float* ybase = y + (size_t)b * (CC * HP) + pix;

        for (int cb = cb0; cb < cb0 + 4; cb++) {
            uint32_t r[32];
            ldtm_x32(r, tmem + cb * 32);
            TC_WAIT_LD();
            #pragma unroll
            for (int q = 0; q < 32; q++)
                ybase[(size_t)(cb * 32 + q) * HP] = __uint_as_float(r[q]);
        }
    }

    __syncthreads();
    if (wid == 0)
        TMEM_DEALLOC(tmem, 256);
#endif  // HAS_TCGEN05
}

// ---------------------------------------------------------------------------
extern "C" void kernel_launch(void* const* d_in, const int* in_sizes, int n_in,
                              void* d_out, int out_size) {
    const float* act = nullptr;
    const float* damp = nullptr;
    const float* width = nullptr;
    for (int i = 0; i < n_in; i++) {
        if (in_sizes[i] > 1024) act = (const float*)d_in[i];
        else if (!damp)  damp  = (const float*)d_in[i];
        else if (!width) width = (const float*)d_in[i];
    }
    float* out = (float*)d_out;

    // Host-side detection: the tc kernel stub (non-sm_103a pass) compiles to a
    // handful of registers; the real one needs far more.
    cudaFuncAttributes fa;
    bool have_tc = (cudaFuncGetAttributes(&fa, inhib_tc_kernel) == cudaSuccess)
                   && fa.numRegs > 24;

    if (have_tc) {
        // single launch: spectral setup is computed inside each CTA
        cudaFuncSetAttribute(inhib_tc_kernel,
                             cudaFuncAttributeMaxDynamicSharedMemorySize, SMEM_TOTAL);
        inhib_tc_kernel<<<NCTAS, 256, SMEM_TOTAL>>>(act, out, damp, width);
    } else {
        setup_kernel<<<1, 256>>>(damp, width);
        cudaFuncSetAttribute(inhib_simt_kernel,
                             cudaFuncAttributeMaxDynamicSharedMemorySize, SIMT_SMEM);
        dim3 sgrid(NTILE, NB);
        inhib_simt_kernel<<<sgrid, 256, SIMT_SMEM>>>(act, out);
    }
}

// round 13
// speedup vs baseline: 1.5771x; 1.0110x over previous
#include <cuda_runtime.h>
#include <math.h>
#include <stdint.h>

#ifndef M_PI
#define M_PI 3.14159265358979323846
#endif

#define CC    256       // channels (circulant size)
#define HP    3136      // 56*56 pixels per batch
#define NB    64        // batch
#define NTOT  (NB * HP) // 200704 global pixel rows

// ---- tcgen05 path geometry (128 px per CTA, 2 CTAs/SM) ----
#define MPIX  128                 // pixels per CTA tile (MMA M)
#define NCTAS (NTOT / MPIX)       // 1568
#define KC    32                  // K elems per chunk (128 B rows of tf32)
#define NCHUNK (CC / KC)          // 8
#define BEXT_ROWS 480             // 224 + 256 rows of extended circulant B

// idesc: dtype F32 (1<<4), atype TF32 (2<<7), btype TF32 (2<<10),
// N=256 -> 32<<17, M=128 -> 8<<24
#define IDESC_TF32 ((1u<<4) | (2u<<7) | (2u<<10) | (32u<<17) | (8u<<24))

// A operand is stored as RAW fp32; the tf32 datapath ignores the low 13 bits
// (truncation toward zero). Mean relative shrink = 2^-10 * ln2 / 2; we cancel
// it by scaling the B operand (mcol) by (1 + that).
#define TRUNC_COMP 1.000339f

// tc smem layout (bytes, dynamic)
#define OFF_TMEMPTR 0
#define OFF_FREEA   8            // freeA0 @8, freeA1 @16 (count 1, commit-driven)
#define OFF_FULL    24           // full0 @24, full1 @32  (count 8, producer arrivals)
#define OFF_DMB     40           // D-done @40 (count 1)
#define OFF_RICK    512          // 32 floats: ricker taps r(e)
#define OFF_MCOL    1024         // 256 floats: inverse-circulant column
#define OFF_ABUF0   2048
#define OFF_ABUF1   18432
#define OFF_BEXT    34816
#define SMEM_TOTAL  96256

// ---- SIMT fallback geometry ----
#define TPIX  64
#define NTILE (HP / TPIX)         // 49
#define SIMT_SMEM ((2 * CC + CC * TPIX) * (int)sizeof(float))

__device__ float g_Mcol[CC];
__device__ int   g_use_tc;

// Only compilation passes with the sm_103a/sm_100a arch-specific feature set
// may ever see tcgen05 PTX (plain sm_103 ptxas rejects it at compile time).
#if defined(__CUDA_ARCH_FEAT_SM103_ALL) || defined(__CUDA_ARCH_FEAT_SM100_ALL)
#define HAS_TCGEN05 1
#else
#define HAS_TCGEN05 0
#endif

// ---------------------------------------------------------------------------
// helpers usable on any target
// ---------------------------------------------------------------------------
__device__ __forceinline__ uint32_t to_tf32(float x) {
    uint32_t u;
    asm("cvt.rna.tf32.f32 %0, %1;" : "=r"(u) : "f"(x));
    return u;
}
#define SWZ128(o) ((o) ^ (((o) >> 3) & 0x70))

// volatile global load: pins issue order so the prefetch stream stays ahead
// of mbar waits.
__device__ __forceinline__ float ldg_v(const float* p) {
    float v;
    asm volatile("ld.global.nc.f32 %0, [%1];" : "=f"(v) : "l"(p));
    return v;
}
// streaming store (evict-first): output is write-once
__device__ __forceinline__ void stg_cs(float* p, float v) {
    asm volatile("st.global.cs.f32 [%0], %1;" :: "l"(p), "f"(v) : "memory");
}

// ---------------------------------------------------------------------------
// Setup kernel (fallback path only): spectral inverse of (I - T) + probe.
// ---------------------------------------------------------------------------
__global__ void setup_kernel(const float* __restrict__ dampp,
                             const float* __restrict__ widthp) {
    __shared__ float ct[CC];
    __shared__ float row0s[CC];
    __shared__ float mus[CC];

    const int t = threadIdx.x;
    if (t == 0) g_use_tc = HAS_TCGEN05;

    const float damp  = *dampp;
    const float width = *widthp;

    ct[t] = (float)cos(2.0 * M_PI * (double)t / 256.0);

    int xe = min(t, CC - t);
    float r = 0.0f;
    if (xe >= 1 && xe <= 31) {
        double w2 = (double)width * (double)width;
        double x2 = (double)xe * (double)xe;
        r = (float)((double)damp * (1.0 - x2 / w2) * exp(-x2 / (2.0 * w2)));
    }
    row0s[t] = r;
    __syncthreads();

    float s = 0.0f;
    for (int d = 0; d < CC; d++) s += row0s[d] * ct[(t * d) & 255];
    mus[t] = 1.0f / (1.0f - s);
    __syncthreads();

    float mc = 0.0f;
    for (int m = 0; m < CC; m++) mc += mus[m] * ct[(t * m) & 255];
    g_Mcol[t] = mc * (1.0f / 256.0f);
}

// ===========================================================================
// SIMT fallback (known-good R1 kernel); runs only when tcgen05 is unavailable
// ===========================================================================
__device__ __forceinline__ unsigned long long ffma2(unsigned long long a,
                                                    unsigned long long b,
                                                    unsigned long long c) {
    unsigned long long d;
    asm("fma.rn.f32x2 %0, %1, %2, %3;" : "=l"(d) : "l"(a), "l"(b), "l"(c));
    return d;
}
__device__ __forceinline__ unsigned long long pack2(float v) {
    unsigned long long d;
    asm("mov.b64 %0, {%1, %1};" : "=l"(d) : "f"(v));
    return d;
}

__global__ __launch_bounds__(256, 2)
void inhib_simt_kernel(const float* __restrict__ x, float* __restrict__ y) {
    if (g_use_tc) return;

    extern __shared__ float smemf[];
    float* Ms2 = smemf;
    float* Xs  = smemf + 2 * CC;

    const int t = threadIdx.x;
    Ms2[t]      = g_Mcol[t];
    Ms2[t + CC] = g_Mcol[t];

    const int b  = blockIdx.y;
    const int p0 = blockIdx.x * TPIX;
    const float* xb = x + (size_t)b * CC * HP + p0;

    const int lr = t >> 4;
    const int lc = (t & 15) * 4;
    #pragma unroll
    for (int rr = 0; rr < 16; rr++) {
        int row = rr * 16 + lr;
        float4 v = *(const float4*)(xb + (size_t)row * HP + lc);
        *(float4*)&Xs[row * TPIX + lc] = v;
    }
    __syncthreads();

    const int i0  = (t >> 3) * 8;
    const int pp0 = (t & 7) * 8;

    unsigned long long acc[8][4];
    #pragma unroll
    for (int ii = 0; ii < 8; ii++)
        #pragma unroll
        for (int pp = 0; pp < 4; pp++) acc[ii][pp] = 0ull;

    #pragma unroll 8
    for (int j = 0; j < CC; j++) {
        const int base = (i0 - j) & 255;
        unsigned long long a2[8];
        #pragma unroll
        for (int ii = 0; ii < 8; ii++) a2[ii] = pack2(Ms2[base + ii]);

        const ulonglong2 bv0 = *(const ulonglong2*)&Xs[j * TPIX + pp0];
        const ulonglong2 bv1 = *(const ulonglong2*)&Xs[j * TPIX + pp0 + 4];
        const unsigned long long b2[4] = {bv0.x, bv0.y, bv1.x, bv1.y};

        #pragma unroll
        for (int ii = 0; ii < 8; ii++)
            #pragma unroll
            for (int pp = 0; pp < 4; pp++)
                acc[ii][pp] = ffma2(a2[ii], b2[pp], acc[ii][pp]);
    }

    float* yb = y + (size_t)b * CC * HP + p0;
    #pragma unroll
    for (int ii = 0; ii < 8; ii++) {
        float* yr = yb + (size_t)(i0 + ii) * HP + pp0;
        #pragma unroll
        for (int pp = 0; pp < 4; pp++)
            *(unsigned long long*)(yr + pp * 2) = acc[ii][pp];
    }
}

// ===========================================================================
// tcgen05 tf32 path (compiled only under the sm_103a feature set)
// ===========================================================================
#if HAS_TCGEN05
__device__ __forceinline__ uint32_t smem_u32(const void* p) {
    uint32_t a;
    asm("{ .reg .u64 t; cvta.to.shared.u64 t, %1; cvt.u32.u64 %0, t; }"
        : "=r"(a) : "l"(p));
    return a;
}
__device__ __forceinline__ uint32_t elect_one() {
    uint32_t p;
    asm volatile("{ .reg .pred p; elect.sync _|p, 0xFFFFFFFF; selp.b32 %0,1,0,p; }"
                 : "=r"(p));
    return p;
}
static __device__ __forceinline__ uint64_t make_desc(uint32_t addr) {
    // SW128 K-major: layout=2, version=1, SBO=64, LBO=1
    const uint64_t base = (uint64_t(2) << 61) | (uint64_t(1) << 46) |
                          (uint64_t(64) << 32) | (uint64_t(1) << 16);
    return base | ((uint64_t)(addr >> 4) & 0x3FFF);
}
__device__ __forceinline__ void mma_tf32_ss(uint32_t d_tmem, uint64_t a_desc,
                                            uint64_t b_desc, uint32_t en) {
    asm volatile(
        "{\n\t"
        ".reg .pred p;\n\t"
        "setp.ne.u32 p, %5, 0;\n\t"
        "tcgen05.mma.cta_group::1.kind::tf32 [%0], %1, %2, %3, {%4, %4, %4, %4}, p;\n\t"
        "}"
        :: "r"(d_tmem), "l"(a_desc), "l"(b_desc), "r"(IDESC_TF32),
           "r"(0u), "r"(en)
        : "memory");
}
#define TMEM_ALLOC(sp, n) \
    asm volatile("tcgen05.alloc.cta_group::1.sync.aligned.shared::cta.b32 [%0], %1;" \
                 :: "r"(sp), "r"((uint32_t)(n)) : "memory")
#define TMEM_DEALLOC(tb, n) \
    asm volatile("tcgen05.dealloc.cta_group::1.sync.aligned.b32 %0, %1;" \
                 :: "r"(tb), "r"((uint32_t)(n)))
#define TMEM_RELINQ() \
    asm volatile("tcgen05.relinquish_alloc_permit.cta_group::1.sync.aligned;")
#define TC_COMMIT(mb) \
    asm volatile("tcgen05.commit.cta_group::1.mbarrier::arrive::one.shared::cluster.b64 [%0];" \
                 :: "r"(mb) : "memory")
#define TC_FENCE_AFTER() asm volatile("tcgen05.fence::after_thread_sync;" ::: "memory")
#define TC_WAIT_LD()     asm volatile("tcgen05.wait::ld.sync.aligned;" ::: "memory")
#define FENCE_ASYNC()    asm volatile("fence.proxy.async.shared::cta;" ::: "memory")
#define MBAR_INIT(mb, n) \
    asm volatile("mbarrier.init.shared.b64 [%0], %1;" :: "r"(mb), "r"((uint32_t)(n)) : "memory")
#define MBAR_ARRIVE(mb) \
    asm volatile("mbarrier.arrive.shared.b64 _, [%0];" :: "r"(mb) : "memory")

__device__ __forceinline__ void mbar_wait(uint32_t mb, uint32_t parity) {
    asm volatile(
        "{\n\t"
        ".reg .pred P1;\n\t"
        "WL_%=:\n\t"
        "mbarrier.try_wait.parity.acquire.cta.shared::cta.b64 P1, [%0], %1, 0x989680;\n\t"
        "@P1 bra.uni WD_%=;\n\t"
        "bra.uni WL_%=;\n\t"
        "WD_%=:\n\t"
        "}"
        :: "r"(mb), "r"(parity) : "memory");
}
__device__ __forceinline__ void ldtm_x32(uint32_t* r, uint32_t ta) {
    asm volatile(
        "tcgen05.ld.sync.aligned.32x32b.x32.b32 "
        "{%0,%1,%2,%3,%4,%5,%6,%7,%8,%9,%10,%11,%12,%13,%14,%15,"
        "%16,%17,%18,%19,%20,%21,%22,%23,%24,%25,%26,%27,%28,%29,%30,%31}, [%32];"
        : "=r"(r[0]), "=r"(r[1]), "=r"(r[2]), "=r"(r[3]),
          "=r"(r[4]), "=r"(r[5]), "=r"(r[6]), "=r"(r[7]),
          "=r"(r[8]), "=r"(r[9]), "=r"(r[10]), "=r"(r[11]),
          "=r"(r[12]), "=r"(r[13]), "=r"(r[14]), "=r"(r[15]),
          "=r"(r[16]), "=r"(r[17]), "=r"(r[18]), "=r"(r[19]),
          "=r"(r[20]), "=r"(r[21]), "=r"(r[22]), "=r"(r[23]),
          "=r"(r[24]), "=r"(r[25]), "=r"(r[26]), "=r"(r[27]),
          "=r"(r[28]), "=r"(r[29]), "=r"(r[30]), "=r"(r[31])
        : "r"(ta));
}
#endif  // HAS_TCGEN05

__global__ __launch_bounds__(256, 2)
void inhib_tc_kernel(const float* __restrict__ x, float* __restrict__ y,
                     const float* __restrict__ dampp,
                     const float* __restrict__ widthp) {
#if HAS_TCGEN05
    extern __shared__ char smem[];
    const uint32_t sb = smem_u32(smem);
    const int t = threadIdx.x;
    const int wid = t >> 5;
    const int lane = t & 31;

    // ---- per-thread staging geometry ----
    const int tp = t & 127;          // tile pixel-row this thread stages
    const int jh = t >> 7;           // 0/1: which 16 j's
    int g0 = blockIdx.x * MPIX + tp;
    int b0 = g0 / HP;
    int pix0 = g0 - b0 * HP;
    const float* xrow = x + (size_t)b0 * (CC * HP) + pix0 + (size_t)(jh * 16) * HP;

    // ---- 3-stage register pipeline: prefetch chunks 0 and 1 now ----
    float v[3][16];
    #pragma unroll
    for (int s = 0; s < 2; s++) {
        const float* xc = xrow + (size_t)(32 * s) * HP;
        #pragma unroll
        for (int jj = 0; jj < 16; jj++)
            v[s][jj] = ldg_v(xc + (size_t)jj * HP);
    }

    if (wid == 0) {
        TMEM_ALLOC(sb + OFF_TMEMPTR, 256);
        TMEM_RELINQ();
    }
    if (t == 0) {
        MBAR_INIT(sb + OFF_FREEA + 0, 1);  // A buf 0 free (commit-driven)
        MBAR_INIT(sb + OFF_FREEA + 8, 1);  // A buf 1 free
        MBAR_INIT(sb + OFF_FULL + 0, 8);   // A buf 0 staged (8 warp arrivals)
        MBAR_INIT(sb + OFF_FULL + 8, 8);   // A buf 1 staged
        MBAR_INIT(sb + OFF_DMB, 1);        // all MMAs done
    }

    // ---- in-CTA spectral setup (fast: symmetry + Chebyshev recurrence) ----
    // lambda_t = 1 - 2*sum_{e=1..31} r(e)*cos(e*theta_t),  theta_t = 2*pi*t/256
    // mcol[t]  = (mu0 + 2*sum_{m=1..128} mu_m*c_m - mu128*(-1)^t) / 256
    // cos terms via 4-chain Chebyshev: c_{k+4} = 2*cos(4*theta)*c_k - c_{k-4}.
    // Only uniform (broadcast) LDS; no gathers.
    {
        float* rS   = (float*)(smem + OFF_RICK);   // 32 f: ricker taps
        float* musS = (float*)(smem + OFF_ABUF0);  // 256 f (scratch, aliased)
        float* mcolS = (float*)(smem + OFF_MCOL);  // 256 f (kept)

        const float damp  = *dampp;
        const float width = *widthp;

        if (t < 32) {
            float r = 0.0f;
            if (t >= 1) {
                float w2 = width * width;
                float x2 = (float)(t * t);
                r = damp * (1.0f - x2 / w2) * expf(-x2 / (2.0f * w2));
            }
            rS[t] = r;
        }

        const float a  = (float)t * (1.0f / 128.0f);   // theta/pi
        const float c1 = cospif(a);
        const float c2 = cospif(2.0f * a);
        const float c3 = cospif(3.0f * a);
        const float c4 = cospif(4.0f * a);
        const float k4 = 2.0f * c4;
        __syncthreads();

        // phase 1: lambda_t (31 terms)
        {
            float cur[4] = {c1, c2, c3, c4};
            float prv[4] = {c3, c2, c1, 1.0f};
            float s = 0.0f;
            #pragma unroll
            for (int i = 0; i < 8; i++) {
                #pragma unroll
                for (int r = 0; r < 4; r++) {
                    const int e = 1 + r + 4 * i;
                    if (e <= 31) s += rS[e] * cur[r];
                    float nx = k4 * cur[r] - prv[r];
                    prv[r] = cur[r];
                    cur[r] = nx;
                }
            }
            musS[t] = 1.0f / (1.0f - 2.0f * s);
        }
        __syncthreads();

        // phase 2: mcol[t] (128 terms, chains cover m = 1..128 exactly once)
        {
            float cur[4] = {c1, c2, c3, c4};
            float prv[4] = {c3, c2, c1, 1.0f};
            float S = 0.0f;
            #pragma unroll 8
            for (int i = 0; i < 32; i++) {
                #pragma unroll
                for (int r = 0; r < 4; r++) {
                    const int m = 1 + r + 4 * i;
                    S += musS[m] * cur[r];
                    float nx = k4 * cur[r] - prv[r];
                    prv[r] = cur[r];
                    cur[r] = nx;
                }
            }
            const float par = (t & 1) ? -1.0f : 1.0f;
            // TRUNC_COMP cancels the mean shrink from storing A as raw fp32
            // (tf32 datapath truncates the low mantissa bits).
            mcolS[t] = (musS[0] + 2.0f * S - musS[128] * par)
                       * (TRUNC_COMP / 256.0f);
        }
        __syncthreads();   // mcol ready; musS scratch (A-buf 0) now dead
    }

    // B_ext[rr][jj] = tf32(mcol[(rr - 224 - jj) & 255]), rr in [0,480);
    // 4 taps packed per STS.128 (conflict-free across the warp).
    {
        const float* mcolS = (const float*)(smem + OFF_MCOL);
        #pragma unroll
        for (int it = 0; it < 15; it++) {
            int g = t + 256 * it;          // group of 4 consecutive jj
            int rr = g >> 3;
            int j0 = (g & 7) * 4;
            int base = rr - 224 - j0;
            uint4 w;
            w.x = to_tf32(mcolS[(base)     & 255]);
            w.y = to_tf32(mcolS[(base - 1) & 255]);
            w.z = to_tf32(mcolS[(base - 2) & 255]);
            w.w = to_tf32(mcolS[(base - 3) & 255]);
            *(uint4*)(smem + OFF_BEXT + SWZ128(rr * 128 + j0 * 4)) = w;
        }
    }
    FENCE_ASYNC();
    __syncthreads();   // mbars + B_ext visible; scratch free for staging

    uint32_t tmem;
    asm volatile("ld.shared.b32 %0, [%1];" : "=r"(tmem) : "r"(sb + OFF_TMEMPTR));

    // ---- main loop: producer warps never block on each other; only the
    //      MMA-issuing warp (warp 0) waits for all 8 staging arrivals ----
    #pragma unroll
    for (int c = 0; c < NCHUNK; c++) {
        if (c + 2 < NCHUNK) {
            const float* xn = xrow + (size_t)(32 * (c + 2)) * HP;
            #pragma unroll
            for (int jj = 0; jj < 16; jj++)
                v[(c + 2) % 3][jj] = ldg_v(xn + (size_t)jj * HP);
        }

        const int buf = c & 1;
        const uint32_t abuf_off = buf ? OFF_ABUF1 : OFF_ABUF0;
        if (c >= 2)
            mbar_wait(sb + OFF_FREEA + 8 * buf, ((c - 2) >> 1) & 1);

        // stage chunk c: RAW fp32 bits (tf32 datapath truncates low bits;
        // mean bias compensated in mcol), packed 4-wide, conflict-free STS.128
        #pragma unroll
        for (int q = 0; q < 4; q++) {
            uint4 w;
            w.x = __float_as_uint(v[c % 3][q * 4 + 0]);
            w.y = __float_as_uint(v[c % 3][q * 4 + 1]);
            w.z = __float_as_uint(v[c % 3][q * 4 + 2]);
            w.w = __float_as_uint(v[c % 3][q * 4 + 3]);
            const int jl = jh * 16 + q * 4;
            *(uint4*)(smem + abuf_off + SWZ128(tp * 128 + jl * 4)) = w;
        }
        FENCE_ASYNC();
        __syncwarp();
        if (elect_one())
            MBAR_ARRIVE(sb + OFF_FULL + 8 * buf);

        if (wid == 0) {
            mbar_wait(sb + OFF_FULL + 8 * buf, (c >> 1) & 1);
            if (elect_one()) {
                uint64_t ad = make_desc(sb + abuf_off);
                uint64_t bd = make_desc(sb + OFF_BEXT + (224 - 32 * c) * 128);
                #pragma unroll
                for (int kk = 0; kk < 4; kk++)
                    mma_tf32_ss(tmem, ad + kk * 2, bd + kk * 2,
                                (c | kk) ? 1u : 0u);
                TC_COMMIT(sb + OFF_FREEA + 8 * buf);
                if (c == NCHUNK - 1)
                    TC_COMMIT(sb + OFF_DMB);
            }
        }
    }

    // ---- epilogue: all warps wait for MMA completion, then stream D out ----
    mbar_wait(sb + OFF_DMB, 0);
    TC_FENCE_AFTER();
    {
        const int sub = wid & 3;
        const int cb0 = (wid >> 2) * 4;
        int g = blockIdx.x * MPIX + sub * 32 + lane;
        int b = g / HP;
        int pix = g - b * HP;
        float* ybase = y + (size_t)b * (CC * HP) + pix;

        for (int cb = cb0; cb < cb0 + 4; cb++) {
            uint32_t r[32];
            ldtm_x32(r, tmem + cb * 32);
            TC_WAIT_LD();
            #pragma unroll
            for (int q = 0; q < 32; q++)
                stg_cs(ybase + (size_t)(cb * 32 + q) * HP, __uint_as_float(r[q]));
        }
    }

    __syncthreads();
    if (wid == 0)
        TMEM_DEALLOC(tmem, 256);
#endif  // HAS_TCGEN05
}

// ---------------------------------------------------------------------------
extern "C" void kernel_launch(void* const* d_in, const int* in_sizes, int n_in,
                              void* d_out, int out_size) {
    const float* act = nullptr;
    const float* damp = nullptr;
    const float* width = nullptr;
    for (int i = 0; i < n_in; i++) {
        if (in_sizes[i] > 1024) act = (const float*)d_in[i];
        else if (!damp)  damp  = (const float*)d_in[i];
        else if (!width) width = (const float*)d_in[i];
    }
    float* out = (float*)d_out;

    // Host-side detection: the tc kernel stub (non-sm_103a pass) compiles to a
    // handful of registers; the real one needs far more.
    cudaFuncAttributes fa;
    bool have_tc = (cudaFuncGetAttributes(&fa, inhib_tc_kernel) == cudaSuccess)
                   && fa.numRegs > 24;

    if (have_tc) {
        // single launch: spectral setup is computed inside each CTA
        cudaFuncSetAttribute(inhib_tc_kernel,
                             cudaFuncAttributeMaxDynamicSharedMemorySize, SMEM_TOTAL);
        inhib_tc_kernel<<<NCTAS, 256, SMEM_TOTAL>>>(act, out, damp, width);
    } else {
        setup_kernel<<<1, 256>>>(damp, width);
        cudaFuncSetAttribute(inhib_simt_kernel,
                             cudaFuncAttributeMaxDynamicSharedMemorySize, SIMT_SMEM);
        dim3 sgrid(NTILE, NB);
        inhib_simt_kernel<<<sgrid, 256, SIMT_SMEM>>>(act, out);
    }
}